// round 1
// baseline (speedup 1.0000x reference)
#include <cuda_runtime.h>
#include <math.h>

#define Bb 16
#define Cc 256
#define CC2 512
#define Ll 8192
#define EPSV 1e-5f
#define TLI 62              // interior columns written per CTA
#define TLC 64              // computed columns (with 1-col halo each side)
#define KB 16               // K-panel depth
#define NTILES ((Ll + TLI - 1) / TLI)   // 133

// Scratch (no allocation allowed in kernel_launch)
__device__ float g_gate[Bb * Cc * Ll];   // SimpleGate output  [B,C,L]
__device__ float g_pool[Bb * Cc];        // global avg pool    [B,C]
__device__ float g_scale[Bb * Cc];       // sigmoid SCA scale  [B,C]

// ---------------------------------------------------------------------------
// K1: LayerNorm + pw1 (C->2C GEMM) + depthwise conv k=3 + SimpleGate
// One CTA handles one (b, l-tile). Computes 64 columns (62 interior + halo).
// ---------------------------------------------------------------------------
__global__ __launch_bounds__(256) void k1_ln_pw1_dw_gate(
    const float* __restrict__ x, const float* __restrict__ gamma,
    const float* __restrict__ beta, const float* __restrict__ w1,
    const float* __restrict__ b1, const float* __restrict__ wd,
    const float* __restrict__ bd)
{
    extern __shared__ float sm[];
    float* yn   = sm;                 // [256][64] normalized input
    float* zb   = yn + Cc * TLC;      // [512][64] pw1 output
    float* wp   = zb + CC2 * TLC;     // [KB][256] weight panel (k-major)
    float* red  = wp + KB * Cc;       // [2][4][64] partial sums
    float* stat = red + 512;          // [2][64] mu, rstd

    const int b    = blockIdx.y;
    const int tile = blockIdx.x;
    const int l0   = tile * TLI - 1;  // global l of local column 0
    const int tid  = threadIdx.x;

    // ---- load x tile (coalesced along l) ----
    for (int i = tid; i < Cc * TLC; i += 256) {
        int c = i >> 6, l = i & 63;
        int lg = l0 + l;
        float v = 0.f;
        if (lg >= 0 && lg < Ll) v = x[(b * Cc + c) * Ll + lg];
        yn[i] = v;
    }
    __syncthreads();

    // ---- LayerNorm stats: 4 threads per column, conflict-free (lanes vary l)
    {
        int l = tid & 63, sub = tid >> 6;
        float s = 0.f, sq = 0.f;
        for (int c = sub; c < Cc; c += 4) {
            float v = yn[c * 64 + l];
            s += v; sq += v * v;
        }
        red[sub * 64 + l]       = s;
        red[256 + sub * 64 + l] = sq;
    }
    __syncthreads();
    if (tid < 64) {
        float s  = red[tid] + red[64 + tid] + red[128 + tid] + red[192 + tid];
        float sq = red[256 + tid] + red[320 + tid] + red[384 + tid] + red[448 + tid];
        float mu  = s * (1.f / Cc);
        float var = sq * (1.f / Cc) - mu * mu;
        stat[tid]      = mu;
        stat[64 + tid] = rsqrtf(var + EPSV);
    }
    __syncthreads();
    for (int i = tid; i < Cc * TLC; i += 256) {
        int c = i >> 6, l = i & 63;
        yn[i] = (yn[i] - stat[l]) * stat[64 + l] * __ldg(&gamma[c]) + __ldg(&beta[c]);
    }
    __syncthreads();

    // ---- pw1 GEMM: z[512][64] = w1[512][256] * yn[256][64], two 256-row passes
    const int mr = (tid >> 3) * 8;   // 32 row-groups of 8
    const int nc = (tid & 7) * 8;    // 8 col-groups of 8
    for (int pass = 0; pass < 2; ++pass) {
        float acc[8][8];
        #pragma unroll
        for (int i = 0; i < 8; i++)
            #pragma unroll
            for (int j = 0; j < 8; j++) acc[i][j] = 0.f;

        const float* wrow = w1 + (pass * Cc + tid) * Cc;
        for (int k0 = 0; k0 < Cc; k0 += KB) {
            __syncthreads();   // previous panel fully consumed
            #pragma unroll
            for (int q = 0; q < KB / 4; ++q) {
                float4 v = *(const float4*)(wrow + k0 + q * 4);
                wp[(q * 4 + 0) * Cc + tid] = v.x;
                wp[(q * 4 + 1) * Cc + tid] = v.y;
                wp[(q * 4 + 2) * Cc + tid] = v.z;
                wp[(q * 4 + 3) * Cc + tid] = v.w;
            }
            __syncthreads();
            #pragma unroll
            for (int kk = 0; kk < KB; ++kk) {
                float4 a0 = *(const float4*)&wp[kk * Cc + mr];
                float4 a1 = *(const float4*)&wp[kk * Cc + mr + 4];
                float4 b0 = *(const float4*)&yn[(k0 + kk) * 64 + nc];
                float4 b1v = *(const float4*)&yn[(k0 + kk) * 64 + nc + 4];
                float av[8] = {a0.x, a0.y, a0.z, a0.w, a1.x, a1.y, a1.z, a1.w};
                float bv[8] = {b0.x, b0.y, b0.z, b0.w, b1v.x, b1v.y, b1v.z, b1v.w};
                #pragma unroll
                for (int i = 0; i < 8; i++)
                    #pragma unroll
                    for (int j = 0; j < 8; j++)
                        acc[i][j] += av[i] * bv[j];
            }
        }
        #pragma unroll
        for (int i = 0; i < 8; i++) {
            float bias = __ldg(&b1[pass * Cc + mr + i]);
            #pragma unroll
            for (int j = 0; j < 8; j++)
                zb[(pass * Cc + mr + i) * 64 + nc + j] = acc[i][j] + bias;
        }
    }
    __syncthreads();

    // ---- depthwise conv (k=3, zero pad at sequence ends) + SimpleGate ----
    for (int idx = tid; idx < Cc * TLI; idx += 256) {
        int m = idx / TLI;
        int l = 1 + (idx - m * TLI);       // local column 1..62
        int lg = l0 + l;                   // global output position
        if (lg >= Ll) continue;            // last tile is partial
        bool lok = (lg > 0), rok = (lg < Ll - 1);

        float zl1 = lok ? zb[m * 64 + l - 1] : 0.f;
        float zc1 = zb[m * 64 + l];
        float zr1 = rok ? zb[m * 64 + l + 1] : 0.f;
        float d1 = __ldg(&wd[m * 3 + 0]) * zl1 + __ldg(&wd[m * 3 + 1]) * zc1 +
                   __ldg(&wd[m * 3 + 2]) * zr1 + __ldg(&bd[m]);

        int m2 = m + Cc;
        float zl2 = lok ? zb[m2 * 64 + l - 1] : 0.f;
        float zc2 = zb[m2 * 64 + l];
        float zr2 = rok ? zb[m2 * 64 + l + 1] : 0.f;
        float d2 = __ldg(&wd[m2 * 3 + 0]) * zl2 + __ldg(&wd[m2 * 3 + 1]) * zc2 +
                   __ldg(&wd[m2 * 3 + 2]) * zr2 + __ldg(&bd[m2]);

        g_gate[(b * Cc + m) * Ll + lg] = d1 * d2;
    }
}

// ---------------------------------------------------------------------------
// K2: global average pool over L for each (b,c)
// ---------------------------------------------------------------------------
__global__ __launch_bounds__(256) void k2_pool()
{
    int row = blockIdx.x;                      // b*C + c
    const float* p = g_gate + (size_t)row * Ll;
    float s = 0.f;
    for (int i = threadIdx.x; i < Ll / 4; i += 256) {
        float4 v = *(const float4*)(p + i * 4);
        s += v.x + v.y + v.z + v.w;
    }
    #pragma unroll
    for (int o = 16; o; o >>= 1) s += __shfl_xor_sync(0xFFFFFFFFu, s, o);
    __shared__ float wsum[8];
    if ((threadIdx.x & 31) == 0) wsum[threadIdx.x >> 5] = s;
    __syncthreads();
    if (threadIdx.x == 0) {
        float t = 0.f;
        #pragma unroll
        for (int w = 0; w < 8; w++) t += wsum[w];
        g_pool[row] = t * (1.f / Ll);
    }
}

// ---------------------------------------------------------------------------
// K3: SCA scale = sigmoid(ws @ pool + bs), one block per batch
// ---------------------------------------------------------------------------
__global__ __launch_bounds__(256) void k3_scale(
    const float* __restrict__ ws, const float* __restrict__ bs)
{
    __shared__ float sp[Cc];
    int b = blockIdx.x;
    sp[threadIdx.x] = g_pool[b * Cc + threadIdx.x];
    __syncthreads();
    const float* wr = ws + threadIdx.x * Cc;
    float acc = __ldg(&bs[threadIdx.x]);
    for (int k = 0; k < Cc; k++) acc += wr[k] * sp[k];
    g_scale[b * Cc + threadIdx.x] = 1.f / (1.f + expf(-acc));
}

// ---------------------------------------------------------------------------
// K4: pw2 GEMM on scaled gate + bias + residual
// ---------------------------------------------------------------------------
__global__ __launch_bounds__(256) void k4_pw2(
    const float* __restrict__ x, const float* __restrict__ w2,
    const float* __restrict__ b2, float* __restrict__ out)
{
    extern __shared__ float sm[];
    float* gs = sm;              // [256][64] scaled gate tile
    float* wp = gs + Cc * 64;    // [KB][256]

    const int b = blockIdx.y, tile = blockIdx.x, tid = threadIdx.x;
    const int l0 = tile * 64;

    for (int i = tid; i < Cc * 64; i += 256) {
        int c = i >> 6, l = i & 63;
        gs[i] = g_gate[(b * Cc + c) * Ll + l0 + l] * __ldg(&g_scale[b * Cc + c]);
    }

    const int mr = (tid >> 3) * 8;
    const int nc = (tid & 7) * 8;
    float acc[8][8];
    #pragma unroll
    for (int i = 0; i < 8; i++)
        #pragma unroll
        for (int j = 0; j < 8; j++) acc[i][j] = 0.f;

    const float* wrow = w2 + tid * Cc;
    for (int k0 = 0; k0 < Cc; k0 += KB) {
        __syncthreads();
        #pragma unroll
        for (int q = 0; q < KB / 4; ++q) {
            float4 v = *(const float4*)(wrow + k0 + q * 4);
            wp[(q * 4 + 0) * Cc + tid] = v.x;
            wp[(q * 4 + 1) * Cc + tid] = v.y;
            wp[(q * 4 + 2) * Cc + tid] = v.z;
            wp[(q * 4 + 3) * Cc + tid] = v.w;
        }
        __syncthreads();
        #pragma unroll
        for (int kk = 0; kk < KB; ++kk) {
            float4 a0 = *(const float4*)&wp[kk * Cc + mr];
            float4 a1 = *(const float4*)&wp[kk * Cc + mr + 4];
            float4 b0 = *(const float4*)&gs[(k0 + kk) * 64 + nc];
            float4 b1v = *(const float4*)&gs[(k0 + kk) * 64 + nc + 4];
            float av[8] = {a0.x, a0.y, a0.z, a0.w, a1.x, a1.y, a1.z, a1.w};
            float bv[8] = {b0.x, b0.y, b0.z, b0.w, b1v.x, b1v.y, b1v.z, b1v.w};
            #pragma unroll
            for (int i = 0; i < 8; i++)
                #pragma unroll
                for (int j = 0; j < 8; j++)
                    acc[i][j] += av[i] * bv[j];
        }
    }

    // epilogue: + b2 + residual x
    #pragma unroll
    for (int i = 0; i < 8; i++) {
        int o = mr + i;
        float bias = __ldg(&b2[o]);
        const float* xr = x + (size_t)(b * Cc + o) * Ll + l0 + nc;
        float* orow = out + (size_t)(b * Cc + o) * Ll + l0 + nc;
        float4 x0 = *(const float4*)xr;
        float4 x1 = *(const float4*)(xr + 4);
        float4 r0, r1;
        r0.x = acc[i][0] + bias + x0.x;  r0.y = acc[i][1] + bias + x0.y;
        r0.z = acc[i][2] + bias + x0.z;  r0.w = acc[i][3] + bias + x0.w;
        r1.x = acc[i][4] + bias + x1.x;  r1.y = acc[i][5] + bias + x1.y;
        r1.z = acc[i][6] + bias + x1.z;  r1.w = acc[i][7] + bias + x1.w;
        *(float4*)orow = r0;
        *(float4*)(orow + 4) = r1;
    }
}

// ---------------------------------------------------------------------------
extern "C" void kernel_launch(void* const* d_in, const int* in_sizes, int n_in,
                              void* d_out, int out_size)
{
    const float* x     = (const float*)d_in[0];
    const float* gamma = (const float*)d_in[1];
    const float* beta  = (const float*)d_in[2];
    const float* w1    = (const float*)d_in[3];
    const float* b1    = (const float*)d_in[4];
    const float* wd    = (const float*)d_in[5];
    const float* bd    = (const float*)d_in[6];
    const float* wsm   = (const float*)d_in[7];
    const float* bs    = (const float*)d_in[8];
    const float* w2    = (const float*)d_in[9];
    const float* b2    = (const float*)d_in[10];
    float* out = (float*)d_out;

    const size_t smem1 = (size_t)(Cc * TLC + CC2 * TLC + KB * Cc + 512 + 128) * sizeof(float); // 215552 B
    const size_t smem4 = (size_t)(Cc * 64 + KB * Cc) * sizeof(float);                          // 81920 B
    cudaFuncSetAttribute(k1_ln_pw1_dw_gate, cudaFuncAttributeMaxDynamicSharedMemorySize, (int)smem1);
    cudaFuncSetAttribute(k4_pw2,            cudaFuncAttributeMaxDynamicSharedMemorySize, (int)smem4);

    dim3 g1(NTILES, Bb);
    k1_ln_pw1_dw_gate<<<g1, 256, smem1>>>(x, gamma, beta, w1, b1, wd, bd);
    k2_pool<<<Bb * Cc, 256>>>();
    k3_scale<<<Bb, 256>>>(wsm, bs);
    dim3 g4(Ll / 64, Bb);
    k4_pw2<<<g4, 256, smem4>>>(x, w2, b2, out);
}

// round 2
// speedup vs baseline: 1.6588x; 1.6588x over previous
#include <cuda_runtime.h>
#include <math.h>

#define Bb 16
#define Cc 256
#define CC2 512
#define Ll 8192
#define EPSV 1e-5f
#define TLI 62              // interior columns written per CTA
#define TLC 64              // computed columns (1-col halo each side)
#define KB 16               // K-panel depth
#define NP (Cc / KB)        // 16 panels
#define NTILES ((Ll + TLI - 1) / TLI)   // 133

typedef unsigned long long ull;

// Scratch (no allocation allowed in kernel_launch)
__device__ float g_gate[Bb * Cc * Ll];   // SimpleGate output  [B,C,L]
__device__ float g_pool[Bb * Cc];        // global avg pool    [B,C]
__device__ float g_scale[Bb * Cc];       // sigmoid SCA scale  [B,C]

// ---- packed f32x2 helpers ----
__device__ __forceinline__ ull pk(float x, float y) {
    ull r; asm("mov.b64 %0,{%1,%2};" : "=l"(r) : "f"(x), "f"(y)); return r;
}
__device__ __forceinline__ ull pk2(float v) {          // duplicate
    ull r; asm("mov.b64 %0,{%1,%1};" : "=l"(r) : "f"(v)); return r;
}
__device__ __forceinline__ void fma2(ull& d, ull a, ull b) {
    asm("fma.rn.f32x2 %0, %1, %2, %0;" : "+l"(d) : "l"(a), "l"(b));
}
__device__ __forceinline__ float2 upk(ull v) {
    float2 r; asm("mov.b64 {%0,%1},%2;" : "=f"(r.x), "=f"(r.y) : "l"(v)); return r;
}

// Inner product step: 2 A-row-pairs x 8 B-cols from smem, packed FFMA2.
// acc[ip][j] holds rows (mr+2ip, mr+2ip+1), col nc+j.
__device__ __forceinline__ void gemm_step(
    ull acc[4][8], const float* __restrict__ wpb, const float* __restrict__ Bm,
    int k0, int mr, int nc)
{
    #pragma unroll
    for (int kk = 0; kk < KB; ++kk) {
        float4 a0 = *(const float4*)&wpb[kk * Cc + mr];
        float4 a1 = *(const float4*)&wpb[kk * Cc + mr + 4];
        float4 b0 = *(const float4*)&Bm[(k0 + kk) * 64 + nc];
        float4 b1 = *(const float4*)&Bm[(k0 + kk) * 64 + nc + 4];
        ull av[4];
        av[0] = pk(a0.x, a0.y); av[1] = pk(a0.z, a0.w);
        av[2] = pk(a1.x, a1.y); av[3] = pk(a1.z, a1.w);
        ull bd[8];
        bd[0] = pk2(b0.x); bd[1] = pk2(b0.y); bd[2] = pk2(b0.z); bd[3] = pk2(b0.w);
        bd[4] = pk2(b1.x); bd[5] = pk2(b1.y); bd[6] = pk2(b1.z); bd[7] = pk2(b1.w);
        #pragma unroll
        for (int ip = 0; ip < 4; ip++)
            #pragma unroll
            for (int j = 0; j < 8; j++)
                fma2(acc[ip][j], av[ip], bd[j]);
    }
}

// ---------------------------------------------------------------------------
// K1: LayerNorm + pw1 (C->2C GEMM) + depthwise conv k=3 + SimpleGate
// ---------------------------------------------------------------------------
__global__ __launch_bounds__(256) void k1_ln_pw1_dw_gate(
    const float* __restrict__ x, const float* __restrict__ gamma,
    const float* __restrict__ beta, const float* __restrict__ w1,
    const float* __restrict__ b1, const float* __restrict__ wd,
    const float* __restrict__ bd_)
{
    extern __shared__ float sm[];
    float* yn   = sm;                 // [256][64] normalized input
    float* zb   = yn + Cc * TLC;      // [512][64] pw1 output
    float* wp   = zb + CC2 * TLC;     // 2 x [KB][256] weight panels
    float* red  = zb;                 // alias: [2][4][64] (zb unused yet)
    float* stat = zb + 512;           // alias: [2][64] mu, rstd

    const int b    = blockIdx.y;
    const int tile = blockIdx.x;
    const int l0   = tile * TLI - 1;
    const int tid  = threadIdx.x;

    // ---- load x tile ----
    for (int i = tid; i < Cc * TLC; i += 256) {
        int c = i >> 6, l = i & 63;
        int lg = l0 + l;
        float v = 0.f;
        if (lg >= 0 && lg < Ll) v = x[(b * Cc + c) * Ll + lg];
        yn[i] = v;
    }
    __syncthreads();

    // ---- LayerNorm stats ----
    {
        int l = tid & 63, sub = tid >> 6;
        float s = 0.f, sq = 0.f;
        for (int c = sub; c < Cc; c += 4) {
            float v = yn[c * 64 + l];
            s += v; sq += v * v;
        }
        red[sub * 64 + l]       = s;
        red[256 + sub * 64 + l] = sq;
    }
    __syncthreads();
    if (tid < 64) {
        float s  = red[tid] + red[64 + tid] + red[128 + tid] + red[192 + tid];
        float sq = red[256 + tid] + red[320 + tid] + red[384 + tid] + red[448 + tid];
        float mu  = s * (1.f / Cc);
        float var = sq * (1.f / Cc) - mu * mu;
        stat[tid]      = mu;
        stat[64 + tid] = rsqrtf(var + EPSV);
    }
    __syncthreads();
    for (int i = tid; i < Cc * TLC; i += 256) {
        int c = i >> 6, l = i & 63;
        yn[i] = (yn[i] - stat[l]) * stat[64 + l] * __ldg(&gamma[c]) + __ldg(&beta[c]);
    }
    __syncthreads();   // stats (aliased in zb) fully consumed before zb written

    // ---- pw1 GEMM: z[512][64] = w1[512][256] * yn[256][64], two passes,
    //      double-buffered weight panels + packed FFMA2
    const int mr = (tid >> 3) * 8;
    const int nc = (tid & 7) * 8;
    for (int pass = 0; pass < 2; ++pass) {
        ull acc[4][8];
        #pragma unroll
        for (int ip = 0; ip < 4; ip++)
            #pragma unroll
            for (int j = 0; j < 8; j++) acc[ip][j] = 0ull;

        const float* wrow = w1 + (pass * Cc + tid) * Cc;

        // prefetch + store panel 0 into buffer 0
        {
            float4 p0 = *(const float4*)(wrow + 0);
            float4 p1 = *(const float4*)(wrow + 4);
            float4 p2 = *(const float4*)(wrow + 8);
            float4 p3 = *(const float4*)(wrow + 12);
            float* w0 = wp;
            w0[0*Cc+tid]=p0.x; w0[1*Cc+tid]=p0.y; w0[2*Cc+tid]=p0.z; w0[3*Cc+tid]=p0.w;
            w0[4*Cc+tid]=p1.x; w0[5*Cc+tid]=p1.y; w0[6*Cc+tid]=p1.z; w0[7*Cc+tid]=p1.w;
            w0[8*Cc+tid]=p2.x; w0[9*Cc+tid]=p2.y; w0[10*Cc+tid]=p2.z; w0[11*Cc+tid]=p2.w;
            w0[12*Cc+tid]=p3.x; w0[13*Cc+tid]=p3.y; w0[14*Cc+tid]=p3.z; w0[15*Cc+tid]=p3.w;
        }

        for (int p = 0; p < NP; ++p) {
            float4 n0, n1, n2, n3;
            if (p + 1 < NP) {
                const float* nw = wrow + (p + 1) * KB;
                n0 = *(const float4*)(nw + 0);
                n1 = *(const float4*)(nw + 4);
                n2 = *(const float4*)(nw + 8);
                n3 = *(const float4*)(nw + 12);
            }
            __syncthreads();   // panel p stores visible; prev buffer free
            gemm_step(acc, wp + (p & 1) * KB * Cc, yn, p * KB, mr, nc);
            if (p + 1 < NP) {
                float* wn = wp + ((p + 1) & 1) * KB * Cc;
                wn[0*Cc+tid]=n0.x; wn[1*Cc+tid]=n0.y; wn[2*Cc+tid]=n0.z; wn[3*Cc+tid]=n0.w;
                wn[4*Cc+tid]=n1.x; wn[5*Cc+tid]=n1.y; wn[6*Cc+tid]=n1.z; wn[7*Cc+tid]=n1.w;
                wn[8*Cc+tid]=n2.x; wn[9*Cc+tid]=n2.y; wn[10*Cc+tid]=n2.z; wn[11*Cc+tid]=n2.w;
                wn[12*Cc+tid]=n3.x; wn[13*Cc+tid]=n3.y; wn[14*Cc+tid]=n3.z; wn[15*Cc+tid]=n3.w;
            }
        }

        #pragma unroll
        for (int ip = 0; ip < 4; ip++) {
            int r0 = pass * Cc + mr + 2 * ip;
            float bia0 = __ldg(&b1[r0]);
            float bia1 = __ldg(&b1[r0 + 1]);
            #pragma unroll
            for (int j = 0; j < 8; j++) {
                float2 v = upk(acc[ip][j]);
                zb[(r0)     * 64 + nc + j] = v.x + bia0;
                zb[(r0 + 1) * 64 + nc + j] = v.y + bia1;
            }
        }
        __syncthreads();   // before next pass reuses wp buffer 0
    }
    __syncthreads();

    // ---- depthwise conv (k=3, zero pad at ends) + SimpleGate ----
    for (int idx = tid; idx < Cc * TLI; idx += 256) {
        int m = idx / TLI;
        int l = 1 + (idx - m * TLI);
        int lg = l0 + l;
        if (lg >= Ll) continue;
        bool lok = (lg > 0), rok = (lg < Ll - 1);

        float zl1 = lok ? zb[m * 64 + l - 1] : 0.f;
        float zc1 = zb[m * 64 + l];
        float zr1 = rok ? zb[m * 64 + l + 1] : 0.f;
        float d1 = __ldg(&wd[m * 3 + 0]) * zl1 + __ldg(&wd[m * 3 + 1]) * zc1 +
                   __ldg(&wd[m * 3 + 2]) * zr1 + __ldg(&bd_[m]);

        int m2 = m + Cc;
        float zl2 = lok ? zb[m2 * 64 + l - 1] : 0.f;
        float zc2 = zb[m2 * 64 + l];
        float zr2 = rok ? zb[m2 * 64 + l + 1] : 0.f;
        float d2 = __ldg(&wd[m2 * 3 + 0]) * zl2 + __ldg(&wd[m2 * 3 + 1]) * zc2 +
                   __ldg(&wd[m2 * 3 + 2]) * zr2 + __ldg(&bd_[m2]);

        g_gate[(b * Cc + m) * Ll + lg] = d1 * d2;
    }
}

// ---------------------------------------------------------------------------
// K2: global average pool over L for each (b,c)
// ---------------------------------------------------------------------------
__global__ __launch_bounds__(256) void k2_pool()
{
    int row = blockIdx.x;
    const float* p = g_gate + (size_t)row * Ll;
    float s = 0.f;
    for (int i = threadIdx.x; i < Ll / 4; i += 256) {
        float4 v = *(const float4*)(p + i * 4);
        s += v.x + v.y + v.z + v.w;
    }
    #pragma unroll
    for (int o = 16; o; o >>= 1) s += __shfl_xor_sync(0xFFFFFFFFu, s, o);
    __shared__ float wsum[8];
    if ((threadIdx.x & 31) == 0) wsum[threadIdx.x >> 5] = s;
    __syncthreads();
    if (threadIdx.x == 0) {
        float t = 0.f;
        #pragma unroll
        for (int w = 0; w < 8; w++) t += wsum[w];
        g_pool[row] = t * (1.f / Ll);
    }
}

// ---------------------------------------------------------------------------
// K3: SCA scale = sigmoid(ws @ pool + bs)
// ---------------------------------------------------------------------------
__global__ __launch_bounds__(256) void k3_scale(
    const float* __restrict__ ws, const float* __restrict__ bs)
{
    __shared__ float sp[Cc];
    int b = blockIdx.x;
    sp[threadIdx.x] = g_pool[b * Cc + threadIdx.x];
    __syncthreads();
    const float* wr = ws + threadIdx.x * Cc;
    float acc = __ldg(&bs[threadIdx.x]);
    for (int k = 0; k < Cc; k++) acc += wr[k] * sp[k];
    g_scale[b * Cc + threadIdx.x] = 1.f / (1.f + expf(-acc));
}

// ---------------------------------------------------------------------------
// K4: pw2 GEMM on scaled gate + bias + residual (double-buffered, FFMA2)
// ---------------------------------------------------------------------------
__global__ __launch_bounds__(256, 2) void k4_pw2(
    const float* __restrict__ x, const float* __restrict__ w2,
    const float* __restrict__ b2, float* __restrict__ out)
{
    extern __shared__ float sm[];
    float* gs = sm;              // [256][64] scaled gate tile
    float* wp = gs + Cc * 64;    // 2 x [KB][256]

    const int b = blockIdx.y, tile = blockIdx.x, tid = threadIdx.x;
    const int l0 = tile * 64;

    for (int i = tid; i < Cc * 64; i += 256) {
        int c = i >> 6, l = i & 63;
        gs[i] = g_gate[(b * Cc + c) * Ll + l0 + l] * __ldg(&g_scale[b * Cc + c]);
    }

    const int mr = (tid >> 3) * 8;
    const int nc = (tid & 7) * 8;
    ull acc[4][8];
    #pragma unroll
    for (int ip = 0; ip < 4; ip++)
        #pragma unroll
        for (int j = 0; j < 8; j++) acc[ip][j] = 0ull;

    const float* wrow = w2 + tid * Cc;
    {
        float4 p0 = *(const float4*)(wrow + 0);
        float4 p1 = *(const float4*)(wrow + 4);
        float4 p2 = *(const float4*)(wrow + 8);
        float4 p3 = *(const float4*)(wrow + 12);
        float* w0 = wp;
        w0[0*Cc+tid]=p0.x; w0[1*Cc+tid]=p0.y; w0[2*Cc+tid]=p0.z; w0[3*Cc+tid]=p0.w;
        w0[4*Cc+tid]=p1.x; w0[5*Cc+tid]=p1.y; w0[6*Cc+tid]=p1.z; w0[7*Cc+tid]=p1.w;
        w0[8*Cc+tid]=p2.x; w0[9*Cc+tid]=p2.y; w0[10*Cc+tid]=p2.z; w0[11*Cc+tid]=p2.w;
        w0[12*Cc+tid]=p3.x; w0[13*Cc+tid]=p3.y; w0[14*Cc+tid]=p3.z; w0[15*Cc+tid]=p3.w;
    }

    for (int p = 0; p < NP; ++p) {
        float4 n0, n1, n2, n3;
        if (p + 1 < NP) {
            const float* nw = wrow + (p + 1) * KB;
            n0 = *(const float4*)(nw + 0);
            n1 = *(const float4*)(nw + 4);
            n2 = *(const float4*)(nw + 8);
            n3 = *(const float4*)(nw + 12);
        }
        __syncthreads();
        gemm_step(acc, wp + (p & 1) * KB * Cc, gs, p * KB, mr, nc);
        if (p + 1 < NP) {
            float* wn = wp + ((p + 1) & 1) * KB * Cc;
            wn[0*Cc+tid]=n0.x; wn[1*Cc+tid]=n0.y; wn[2*Cc+tid]=n0.z; wn[3*Cc+tid]=n0.w;
            wn[4*Cc+tid]=n1.x; wn[5*Cc+tid]=n1.y; wn[6*Cc+tid]=n1.z; wn[7*Cc+tid]=n1.w;
            wn[8*Cc+tid]=n2.x; wn[9*Cc+tid]=n2.y; wn[10*Cc+tid]=n2.z; wn[11*Cc+tid]=n2.w;
            wn[12*Cc+tid]=n3.x; wn[13*Cc+tid]=n3.y; wn[14*Cc+tid]=n3.z; wn[15*Cc+tid]=n3.w;
        }
    }

    // epilogue: + b2 + residual x
    #pragma unroll
    for (int ip = 0; ip < 4; ip++) {
        #pragma unroll
        for (int e = 0; e < 2; e++) {
            int o = mr + 2 * ip + e;
            float bias = __ldg(&b2[o]);
            const float* xr = x + (size_t)(b * Cc + o) * Ll + l0 + nc;
            float* orow = out + (size_t)(b * Cc + o) * Ll + l0 + nc;
            float4 x0 = *(const float4*)xr;
            float4 x1 = *(const float4*)(xr + 4);
            float r[8];
            #pragma unroll
            for (int j = 0; j < 8; j++) {
                float2 v = upk(acc[ip][j]);
                r[j] = (e == 0 ? v.x : v.y) + bias;
            }
            float4 o0, o1;
            o0.x = r[0] + x0.x; o0.y = r[1] + x0.y; o0.z = r[2] + x0.z; o0.w = r[3] + x0.w;
            o1.x = r[4] + x1.x; o1.y = r[5] + x1.y; o1.z = r[6] + x1.z; o1.w = r[7] + x1.w;
            *(float4*)orow = o0;
            *(float4*)(orow + 4) = o1;
        }
    }
}

// ---------------------------------------------------------------------------
extern "C" void kernel_launch(void* const* d_in, const int* in_sizes, int n_in,
                              void* d_out, int out_size)
{
    const float* x     = (const float*)d_in[0];
    const float* gamma = (const float*)d_in[1];
    const float* beta  = (const float*)d_in[2];
    const float* w1    = (const float*)d_in[3];
    const float* b1    = (const float*)d_in[4];
    const float* wd    = (const float*)d_in[5];
    const float* bd    = (const float*)d_in[6];
    const float* wsm   = (const float*)d_in[7];
    const float* bs    = (const float*)d_in[8];
    const float* w2    = (const float*)d_in[9];
    const float* b2    = (const float*)d_in[10];
    float* out = (float*)d_out;

    const size_t smem1 = (size_t)(Cc * TLC + CC2 * TLC + 2 * KB * Cc) * sizeof(float); // 229376 B
    const size_t smem4 = (size_t)(Cc * 64 + 2 * KB * Cc) * sizeof(float);              // 98304 B
    cudaFuncSetAttribute(k1_ln_pw1_dw_gate, cudaFuncAttributeMaxDynamicSharedMemorySize, (int)smem1);
    cudaFuncSetAttribute(k4_pw2,            cudaFuncAttributeMaxDynamicSharedMemorySize, (int)smem4);

    dim3 g1(NTILES, Bb);
    k1_ln_pw1_dw_gate<<<g1, 256, smem1>>>(x, gamma, beta, w1, b1, wd, bd);
    k2_pool<<<Bb * Cc, 256>>>();
    k3_scale<<<Bb, 256>>>(wsm, bs);
    dim3 g4(Ll / 64, Bb);
    k4_pw2<<<g4, 256, smem4>>>(x, w2, b2, out);
}

// round 4
// speedup vs baseline: 2.6669x; 1.6077x over previous
#include <cuda_runtime.h>
#include <cuda_bf16.h>
#include <math.h>
#include <stdint.h>

#define Bb 16
#define Cc 256
#define CC2 512
#define Ll 8192
#define EPSV 1e-5f
#define TLI 62
#define NTILES 133           // ceil(8192/62)

// scratch
__device__ float g_gate[Bb * Cc * Ll];
__device__ float g_pool[Bb * Cc];
__device__ float g_scale[Bb * Cc];
// weights, bf16 split, panel-major: [p = k/16][m][16]
__device__ __nv_bfloat16 g_w1h[131072], g_w1l[131072];
__device__ __nv_bfloat16 g_w2h[65536],  g_w2l[65536];

// ---------------- helpers ----------------
__device__ __forceinline__ uint32_t smem_u32(const void* p) {
    uint32_t a;
    asm("{ .reg .u64 t; cvta.to.shared.u64 t, %1; cvt.u32.u64 %0, t; }" : "=r"(a) : "l"(p));
    return a;
}
__device__ __forceinline__ void ldsm4(uint32_t* r, uint32_t addr) {
    asm volatile("ldmatrix.sync.aligned.m8n8.x4.shared.b16 {%0,%1,%2,%3}, [%4];"
        : "=r"(r[0]), "=r"(r[1]), "=r"(r[2]), "=r"(r[3]) : "r"(addr));
}
__device__ __forceinline__ void mma16816(float* c, const uint32_t* a, const uint32_t* b) {
    asm volatile("mma.sync.aligned.m16n8k16.row.col.f32.bf16.bf16.f32 "
        "{%0,%1,%2,%3}, {%4,%5,%6,%7}, {%8,%9}, {%0,%1,%2,%3};"
        : "+f"(c[0]), "+f"(c[1]), "+f"(c[2]), "+f"(c[3])
        : "r"(a[0]), "r"(a[1]), "r"(a[2]), "r"(a[3]), "r"(b[0]), "r"(b[1]));
}
__device__ __forceinline__ void bf16_split(float v, unsigned short* hi, unsigned short* lo) {
    __nv_bfloat16 h = __float2bfloat16(v);
    __nv_bfloat16 l = __float2bfloat16(v - __bfloat162float(h));
    *hi = *reinterpret_cast<unsigned short*>(&h);
    *lo = *reinterpret_cast<unsigned short*>(&l);
}
// B-tile byte offset with per-row swizzle: row l (n dim), channel c (k dim).
// row stride 512B; 16B-group index XORed with (l&7) -> conflict-free ldmatrix.
__device__ __forceinline__ uint32_t bswz(int l, int c) {
    return (uint32_t)(l * 512 + ((((c >> 3) ^ (l & 7)) << 4) | ((c & 7) * 2)));
}

// ---------------------------------------------------------------------------
// K0: split weights to bf16 hi/lo, panel-major [k/16][m][16]
// ---------------------------------------------------------------------------
__global__ __launch_bounds__(256) void k0_split(const float* __restrict__ w1,
                                                const float* __restrict__ w2)
{
    int idx = blockIdx.x * 256 + threadIdx.x;
    if (idx < 131072) {
        int m = idx >> 8, k = idx & 255;
        unsigned short h, l;
        bf16_split(w1[idx], &h, &l);
        int off = ((k >> 4) * 512 + m) * 16 + (k & 15);
        *(unsigned short*)&g_w1h[off] = h;
        *(unsigned short*)&g_w1l[off] = l;
    } else {
        idx -= 131072;
        if (idx < 65536) {
            int m = idx >> 8, k = idx & 255;
            unsigned short h, l;
            bf16_split(w2[idx], &h, &l);
            int off = ((k >> 4) * 256 + m) * 16 + (k & 15);
            *(unsigned short*)&g_w2h[off] = h;
            *(unsigned short*)&g_w2l[off] = l;
        }
    }
}

// ---------------------------------------------------------------------------
// K1: LN + pw1 (mma.sync bf16-split) + depthwise conv + SimpleGate -> g_gate
// smem map (bytes):
//   [0,65536)        B tile: hi 32KB | lo 32KB    ([64 l][256 c] swizzled)
//   [65536,98304)    A panels: 2 bufs x (hi 8KB | lo 8KB)
//   [98304,163840)   z1 [256][64] f32 (aliased as xf staging first)
//   [163840,229376)  z2 [256][64] f32
//   [229376,231936)  red[512] + stat[128]
// ---------------------------------------------------------------------------
#define K1_B   0
#define K1_A   65536
#define K1_Z1  98304
#define K1_Z2  163840
#define K1_RED 229376
#define K1_SMEM 231936

__global__ __launch_bounds__(256) void k1_ln_pw1(
    const float* __restrict__ x, const float* __restrict__ gamma,
    const float* __restrict__ beta, const float* __restrict__ b1,
    const float* __restrict__ wd, const float* __restrict__ bd_)
{
    extern __shared__ char sm[];
    float* xf   = (float*)(sm + K1_Z1);
    float* red  = (float*)(sm + K1_RED);
    float* stat = (float*)(sm + K1_RED + 2048);
    const uint32_t smb = smem_u32(sm);
    const int b    = blockIdx.y;
    const int tile = blockIdx.x;
    const int l0   = tile * TLI - 1;
    const int tid  = threadIdx.x;
    const int w    = tid >> 5, lane = tid & 31;

    // ---- load x tile [256 c][64 l] ----
    for (int i = tid; i < Cc * 64; i += 256) {
        int c = i >> 6, l = i & 63;
        int lg = l0 + l;
        float v = 0.f;
        if (lg >= 0 && lg < Ll) v = x[(b * Cc + c) * Ll + lg];
        xf[i] = v;
    }
    __syncthreads();

    // ---- LN stats ----
    {
        int l = tid & 63, sub = tid >> 6;
        float s = 0.f, sq = 0.f;
        for (int c = sub; c < Cc; c += 4) {
            float v = xf[c * 64 + l];
            s += v; sq += v * v;
        }
        red[sub * 64 + l] = s;
        red[256 + sub * 64 + l] = sq;
    }
    __syncthreads();
    if (tid < 64) {
        float s  = red[tid] + red[64 + tid] + red[128 + tid] + red[192 + tid];
        float sq = red[256 + tid] + red[320 + tid] + red[384 + tid] + red[448 + tid];
        float mu = s * (1.f / Cc);
        float var = sq * (1.f / Cc) - mu * mu;
        stat[tid] = mu;
        stat[64 + tid] = rsqrtf(var + EPSV);
    }
    __syncthreads();

    // ---- normalize + bf16 split -> B tile [l][c] swizzled ----
    for (int i = tid; i < 128 * 64; i += 256) {
        int cp = i >> 6, l = i & 63;
        int c = cp * 2;
        float mu = stat[l], rs = stat[64 + l];
        float v0 = (xf[c * 64 + l] - mu) * rs * __ldg(&gamma[c]) + __ldg(&beta[c]);
        float v1 = (xf[(c + 1) * 64 + l] - mu) * rs * __ldg(&gamma[c + 1]) + __ldg(&beta[c + 1]);
        unsigned short h0, h1, lo0, lo1;
        bf16_split(v0, &h0, &lo0);
        bf16_split(v1, &h1, &lo1);
        uint32_t by = bswz(l, c);
        *(uint32_t*)(sm + K1_B + by)         = (uint32_t)h0 | ((uint32_t)h1 << 16);
        *(uint32_t*)(sm + K1_B + 32768 + by) = (uint32_t)lo0 | ((uint32_t)lo1 << 16);
    }
    __syncthreads();   // B ready; xf (z1 region) now reusable

    // ---- fragment addressing ----
    const int lr  = lane & 7;
    const int gb0 = (lane >> 3) & 1;     // A: k-half   B: k-half
    const int gb1 = lane >> 4;           // A: row+8    B: row+8
    const uint32_t aBase = smb + K1_A + (uint32_t)((w * 32 + gb0 * 8 + lr) * 32 + gb1 * 16);
    uint32_t bBase[4];
    #pragma unroll
    for (int bp = 0; bp < 4; bp++)
        bBase[bp] = smb + K1_B + (uint32_t)((bp * 16 + gb1 * 8 + lr) * 512);

    // ---- GEMM: two M-passes of 256 rows ----
    for (int pass = 0; pass < 2; ++pass) {
        float acc[2][8][4];
        #pragma unroll
        for (int mt = 0; mt < 2; mt++)
            #pragma unroll
            for (int nt = 0; nt < 8; nt++)
                #pragma unroll
                for (int q = 0; q < 4; q++) acc[mt][nt][q] = 0.f;

        const int4* srcH = (const int4*)g_w1h + (size_t)(pass * 256 + tid) * 2;
        const int4* srcL = (const int4*)g_w1l + (size_t)(pass * 256 + tid) * 2;

        // panel 0 -> buf 0
        {
            int4 h0 = srcH[0], h1 = srcH[1], q0 = srcL[0], q1 = srcL[1];
            int4* d = (int4*)(sm + K1_A) + tid * 2;
            d[0] = h0; d[1] = h1; d[512] = q0; d[513] = q1;
        }

        for (int p = 0; p < 16; ++p) {
            int4 nh0, nh1, nl0, nl1;
            if (p < 15) {
                nh0 = srcH[(p + 1) * 1024]; nh1 = srcH[(p + 1) * 1024 + 1];
                nl0 = srcL[(p + 1) * 1024]; nl1 = srcL[(p + 1) * 1024 + 1];
            }
            __syncthreads();
            const uint32_t ab = aBase + (uint32_t)((p & 1) * 16384);
            uint32_t Ah[2][4], Al[2][4];
            ldsm4(Ah[0], ab);
            ldsm4(Ah[1], ab + 512);
            ldsm4(Al[0], ab + 8192);
            ldsm4(Al[1], ab + 8192 + 512);
            uint32_t kx = (uint32_t)(((p * 2 + gb0) ^ lr) << 4);
            uint32_t Bh[16], Bl[16];
            #pragma unroll
            for (int bp = 0; bp < 4; bp++) {
                ldsm4(&Bh[bp * 4], bBase[bp] + kx);
                ldsm4(&Bl[bp * 4], bBase[bp] + 32768 + kx);
            }
            #pragma unroll
            for (int mt = 0; mt < 2; mt++)
                #pragma unroll
                for (int nt = 0; nt < 8; nt++) {
                    mma16816(acc[mt][nt], Ah[mt], &Bh[nt * 2]);
                    mma16816(acc[mt][nt], Ah[mt], &Bl[nt * 2]);
                    mma16816(acc[mt][nt], Al[mt], &Bh[nt * 2]);
                }
            if (p < 15) {
                int4* d = (int4*)(sm + K1_A + ((p + 1) & 1) * 16384) + tid * 2;
                d[0] = nh0; d[1] = nh1; d[512] = nl0; d[513] = nl1;
            }
        }

        // store z (+bias) to smem
        float* zb = (float*)(sm + (pass == 0 ? K1_Z1 : K1_Z2));
        #pragma unroll
        for (int mt = 0; mt < 2; mt++) {
            int r = w * 32 + mt * 16 + (lane >> 2);
            float bi0 = __ldg(&b1[pass * 256 + r]);
            float bi1 = __ldg(&b1[pass * 256 + r + 8]);
            #pragma unroll
            for (int nt = 0; nt < 8; nt++) {
                int c = nt * 8 + (lane & 3) * 2;
                zb[r * 64 + c]           = acc[mt][nt][0] + bi0;
                zb[r * 64 + c + 1]       = acc[mt][nt][1] + bi0;
                zb[(r + 8) * 64 + c]     = acc[mt][nt][2] + bi1;
                zb[(r + 8) * 64 + c + 1] = acc[mt][nt][3] + bi1;
            }
        }
    }
    __syncthreads();

    // ---- depthwise conv (k=3, zero pad at ends) + SimpleGate ----
    float* z1 = (float*)(sm + K1_Z1);
    float* z2 = (float*)(sm + K1_Z2);
    for (int idx = tid; idx < Cc * TLI; idx += 256) {
        int m = idx / TLI;
        int l = 1 + (idx - m * TLI);
        int lg = l0 + l;
        if (lg >= Ll) continue;
        bool lok = (lg > 0), rok = (lg < Ll - 1);

        float a_l = lok ? z1[m * 64 + l - 1] : 0.f;
        float a_c = z1[m * 64 + l];
        float a_r = rok ? z1[m * 64 + l + 1] : 0.f;
        float d1 = __ldg(&wd[m * 3 + 0]) * a_l + __ldg(&wd[m * 3 + 1]) * a_c +
                   __ldg(&wd[m * 3 + 2]) * a_r + __ldg(&bd_[m]);

        int m2 = m + Cc;
        float b_l = lok ? z2[m * 64 + l - 1] : 0.f;
        float b_c = z2[m * 64 + l];
        float b_r = rok ? z2[m * 64 + l + 1] : 0.f;
        float d2 = __ldg(&wd[m2 * 3 + 0]) * b_l + __ldg(&wd[m2 * 3 + 1]) * b_c +
                   __ldg(&wd[m2 * 3 + 2]) * b_r + __ldg(&bd_[m2]);

        g_gate[(size_t)(b * Cc + m) * Ll + lg] = d1 * d2;
    }
}

// ---------------------------------------------------------------------------
// K2: global average pool
// ---------------------------------------------------------------------------
__global__ __launch_bounds__(256) void k2_pool()
{
    int row = blockIdx.x;
    const float* p = g_gate + (size_t)row * Ll;
    float s = 0.f;
    for (int i = threadIdx.x; i < Ll / 4; i += 256) {
        float4 v = *(const float4*)(p + i * 4);
        s += v.x + v.y + v.z + v.w;
    }
    #pragma unroll
    for (int o = 16; o; o >>= 1) s += __shfl_xor_sync(0xFFFFFFFFu, s, o);
    __shared__ float wsum[8];
    if ((threadIdx.x & 31) == 0) wsum[threadIdx.x >> 5] = s;
    __syncthreads();
    if (threadIdx.x == 0) {
        float t = 0.f;
        #pragma unroll
        for (int q = 0; q < 8; q++) t += wsum[q];
        g_pool[row] = t * (1.f / Ll);
    }
}

// ---------------------------------------------------------------------------
// K3: SCA scale
// ---------------------------------------------------------------------------
__global__ __launch_bounds__(256) void k3_scale(
    const float* __restrict__ ws, const float* __restrict__ bs)
{
    __shared__ float sp[Cc];
    int b = blockIdx.x;
    sp[threadIdx.x] = g_pool[b * Cc + threadIdx.x];
    __syncthreads();
    const float* wr = ws + threadIdx.x * Cc;
    float acc = __ldg(&bs[threadIdx.x]);
    for (int k = 0; k < Cc; k++) acc += wr[k] * sp[k];
    g_scale[b * Cc + threadIdx.x] = 1.f / (1.f + expf(-acc));
}

// ---------------------------------------------------------------------------
// K4: pw2 (mma.sync bf16-split) + bias + residual
// smem: [0,65536) B hi|lo; [65536,98304) A bufs; [98304,163840) z [256][64]
// ---------------------------------------------------------------------------
#define K4_B 0
#define K4_A 65536
#define K4_Z 98304
#define K4_SMEM 163840

__global__ __launch_bounds__(256) void k4_pw2(
    const float* __restrict__ x, const float* __restrict__ b2,
    float* __restrict__ out)
{
    extern __shared__ char sm[];
    const uint32_t smb = smem_u32(sm);
    const int b = blockIdx.y, tile = blockIdx.x, tid = threadIdx.x;
    const int w = tid >> 5, lane = tid & 31;
    const int l0 = tile * 64;

    // ---- B tile: gate*scale -> bf16 split [l 64][c 256] swizzled ----
    for (int i = tid; i < 128 * 64; i += 256) {
        int cp = i >> 6, l = i & 63;
        int c = cp * 2;
        float v0 = g_gate[(size_t)(b * Cc + c) * Ll + l0 + l] * __ldg(&g_scale[b * Cc + c]);
        float v1 = g_gate[(size_t)(b * Cc + c + 1) * Ll + l0 + l] * __ldg(&g_scale[b * Cc + c + 1]);
        unsigned short h0, h1, lo0, lo1;
        bf16_split(v0, &h0, &lo0);
        bf16_split(v1, &h1, &lo1);
        uint32_t by = bswz(l, c);
        *(uint32_t*)(sm + K4_B + by)         = (uint32_t)h0 | ((uint32_t)h1 << 16);
        *(uint32_t*)(sm + K4_B + 32768 + by) = (uint32_t)lo0 | ((uint32_t)lo1 << 16);
    }

    const int lr  = lane & 7;
    const int gb0 = (lane >> 3) & 1;
    const int gb1 = lane >> 4;
    const uint32_t aBase = smb + K4_A + (uint32_t)((w * 32 + gb0 * 8 + lr) * 32 + gb1 * 16);
    uint32_t bBase[4];
    #pragma unroll
    for (int bp = 0; bp < 4; bp++)
        bBase[bp] = smb + K4_B + (uint32_t)((bp * 16 + gb1 * 8 + lr) * 512);

    float acc[2][8][4];
    #pragma unroll
    for (int mt = 0; mt < 2; mt++)
        #pragma unroll
        for (int nt = 0; nt < 8; nt++)
            #pragma unroll
            for (int q = 0; q < 4; q++) acc[mt][nt][q] = 0.f;

    const int4* srcH = (const int4*)g_w2h + (size_t)tid * 2;
    const int4* srcL = (const int4*)g_w2l + (size_t)tid * 2;
    {
        int4 h0 = srcH[0], h1 = srcH[1], q0 = srcL[0], q1 = srcL[1];
        int4* d = (int4*)(sm + K4_A) + tid * 2;
        d[0] = h0; d[1] = h1; d[512] = q0; d[513] = q1;
    }
    __syncthreads();   // also covers B-tile writes

    for (int p = 0; p < 16; ++p) {
        int4 nh0, nh1, nl0, nl1;
        if (p < 15) {
            nh0 = srcH[(p + 1) * 512]; nh1 = srcH[(p + 1) * 512 + 1];
            nl0 = srcL[(p + 1) * 512]; nl1 = srcL[(p + 1) * 512 + 1];
        }
        if (p > 0) __syncthreads();
        const uint32_t ab = aBase + (uint32_t)((p & 1) * 16384);
        uint32_t Ah[2][4], Al[2][4];
        ldsm4(Ah[0], ab);
        ldsm4(Ah[1], ab + 512);
        ldsm4(Al[0], ab + 8192);
        ldsm4(Al[1], ab + 8192 + 512);
        uint32_t kx = (uint32_t)(((p * 2 + gb0) ^ lr) << 4);
        uint32_t Bh[16], Bl[16];
        #pragma unroll
        for (int bp = 0; bp < 4; bp++) {
            ldsm4(&Bh[bp * 4], bBase[bp] + kx);
            ldsm4(&Bl[bp * 4], bBase[bp] + 32768 + kx);
        }
        #pragma unroll
        for (int mt = 0; mt < 2; mt++)
            #pragma unroll
            for (int nt = 0; nt < 8; nt++) {
                mma16816(acc[mt][nt], Ah[mt], &Bh[nt * 2]);
                mma16816(acc[mt][nt], Ah[mt], &Bl[nt * 2]);
                mma16816(acc[mt][nt], Al[mt], &Bh[nt * 2]);
            }
        if (p < 15) {
            int4* d = (int4*)(sm + K4_A + ((p + 1) & 1) * 16384) + tid * 2;
            d[0] = nh0; d[1] = nh1; d[512] = nl0; d[513] = nl1;
        }
    }

    // stage z in smem for coalesced output
    float* zb = (float*)(sm + K4_Z);
    #pragma unroll
    for (int mt = 0; mt < 2; mt++) {
        int r = w * 32 + mt * 16 + (lane >> 2);
        #pragma unroll
        for (int nt = 0; nt < 8; nt++) {
            int c = nt * 8 + (lane & 3) * 2;
            zb[r * 64 + c]           = acc[mt][nt][0];
            zb[r * 64 + c + 1]       = acc[mt][nt][1];
            zb[(r + 8) * 64 + c]     = acc[mt][nt][2];
            zb[(r + 8) * 64 + c + 1] = acc[mt][nt][3];
        }
    }
    __syncthreads();

    // out = z + b2 + x   (coalesced float4)
    const float4* z4 = (const float4*)zb;
    for (int i = tid; i < Cc * 16; i += 256) {
        int m = i >> 4, lq = i & 15;
        float bias = __ldg(&b2[m]);
        float4 zv = z4[i];
        const float* xr = x + (size_t)(b * Cc + m) * Ll + l0 + lq * 4;
        float4 xv = *(const float4*)xr;
        float4 ov;
        ov.x = zv.x + bias + xv.x;
        ov.y = zv.y + bias + xv.y;
        ov.z = zv.z + bias + xv.z;
        ov.w = zv.w + bias + xv.w;
        *(float4*)(out + (size_t)(b * Cc + m) * Ll + l0 + lq * 4) = ov;
    }
}

// ---------------------------------------------------------------------------
extern "C" void kernel_launch(void* const* d_in, const int* in_sizes, int n_in,
                              void* d_out, int out_size)
{
    const float* x     = (const float*)d_in[0];
    const float* gamma = (const float*)d_in[1];
    const float* beta  = (const float*)d_in[2];
    const float* w1    = (const float*)d_in[3];
    const float* b1    = (const float*)d_in[4];
    const float* wd    = (const float*)d_in[5];
    const float* bd    = (const float*)d_in[6];
    const float* wsm   = (const float*)d_in[7];
    const float* bs    = (const float*)d_in[8];
    const float* w2    = (const float*)d_in[9];
    const float* b2    = (const float*)d_in[10];
    float* out = (float*)d_out;

    cudaFuncSetAttribute(k1_ln_pw1, cudaFuncAttributeMaxDynamicSharedMemorySize, K1_SMEM);
    cudaFuncSetAttribute(k4_pw2,    cudaFuncAttributeMaxDynamicSharedMemorySize, K4_SMEM);

    k0_split<<<768, 256>>>(w1, w2);
    dim3 g1(NTILES, Bb);
    k1_ln_pw1<<<g1, 256, K1_SMEM>>>(x, gamma, beta, b1, wd, bd);
    k2_pool<<<Bb * Cc, 256>>>();
    k3_scale<<<Bb, 256>>>(wsm, bs);
    dim3 g4(Ll / 64, Bb);
    k4_pw2<<<g4, 256, K4_SMEM>>>(x, b2, out);
}